// round 15
// baseline (speedup 1.0000x reference)
#include <cuda_runtime.h>
#include <cuda_fp16.h>
#include <cstdint>

#define NN 100000
#define EE 1600000
#define HF 128           // HEADS * OUT_F
#define NB_SCAN 98       // ceil(NN/1024)
#define BM 32            // rows per gemm block
#define NGEMM 3125       // ceil(NN/32) total gemm blocks
#define NG1 1250         // gemm blocks overlapped with count
#define NG2 (NGEMM - NG1)
#define NCOUNT 6250      // ceil(EE/256)
#define NSCAT 6641       // ceil((EE+NN)/256)
#define XS_STRIDE 144    // halves per row (128 + 16 pad)

// ---------------- scratch (statics zero-initialized at load) -----------------
__device__ unsigned int g_hh[NN * 64]; // 25.6 MB : h in half2 (64 x uint per row)
__device__ float  g_asrc[NN * 4];
__device__ float  g_adst[NN * 4];
__device__ int    g_deg[NN];           // scan re-zeroes after use (replay-safe)
__device__ int    g_cursor[NN];
__device__ int    g_rowstart[NN + 1];
__device__ int    g_srcs[EE + NN];
__device__ unsigned long long g_lb[NB_SCAN];  // lookback: (flag<<32)|blocksum
__device__ uint2  g_Whp[128 * 8 * 4];  // W in fp16 B-fragment order (32 KB)
__device__ int    g_is64;

// ---------------- kernel 1: detect + lb clear + W fp16 fragment pack ---------
__global__ __launch_bounds__(256) void pack_kernel(
    const int* ei32, const float* __restrict__ W) {
    const int bid = blockIdx.x, tid = threadIdx.x;
    if (bid == 0) {
        __shared__ int nz;
        if (tid == 0) nz = 0;
        __syncthreads();
        if (ei32[tid * 2 + 1] != 0) atomicAdd(&nz, 1);  // odd words zero => int64
        __syncthreads();
        if (tid == 0) g_is64 = (nz == 0) ? 1 : 0;
        if (tid < NB_SCAN) g_lb[tid] = 0ULL;
        return;
    }
    int e = (bid - 1) * 256 + tid;       // < 4096 : (n, ks, tig)
    int n = e >> 5, r = e & 31, ks = r >> 2, tg = r & 3;
    int k0 = ks * 16 + tg * 2;
    half2 lo = __floats2half2_rn(W[k0 * HF + n],       W[(k0 + 1) * HF + n]);
    half2 hi = __floats2half2_rn(W[(k0 + 8) * HF + n], W[(k0 + 9) * HF + n]);
    g_Whp[e] = make_uint2(*(unsigned int*)&lo, *(unsigned int*)&hi);
}

// ---------------- GEMM tile body: fp16 mma m16n8k16, 256 thr, 8 warps --------
// BM=32; warp tile 16x32: wm = warp>>2 (which 16-row half), head = warp&3
// smem: per row 128 halves permuted so LDS.64 yields (a0,a2) fragment pairs;
// 4-slot XOR swizzle (slot ^= row&3) -> 2-way-floor bank access
__device__ __forceinline__ void gemm_tile(
    int blk0, int tid, half* xs, const float* __restrict__ x,
    const float* __restrict__ att_src, const float* __restrict__ att_dst) {
#pragma unroll
    for (int it = 0; it < 4; it++) {
        int fidx = it * 256 + tid;            // float4 index, 1024 total
        int row = fidx >> 5, c4 = (fidx & 31) * 4;
        float4 v = make_float4(0.f, 0.f, 0.f, 0.f);
        if (blk0 + row < NN) v = *(const float4*)(x + (size_t)(blk0 + row) * HF + c4);
        int base = c4 & ~15;
        int q  = (c4 >> 1) & 3;               // logical slot of (k, k+1)
        int h2 = (c4 >> 3) & 1;               // within-slot offset (k vs k+8 group)
        int sw = row & 3;
        half* rp = xs + row * XS_STRIDE + base;
        *(half2*)(rp + (q ^ sw) * 4 + h2 * 2)       = __floats2half2_rn(v.x, v.y);
        *(half2*)(rp + ((q + 1) ^ sw) * 4 + h2 * 2) = __floats2half2_rn(v.z, v.w);
    }
    __syncthreads();

    const int warp = tid >> 5, lane = tid & 31;
    const int grp = lane >> 2, tig = lane & 3;
    const int wm = warp >> 2, head = warp & 3;
    const int n0 = head * 32;
    const int rA = wm * 16 + grp;
    const int soff = (tig ^ (grp & 3)) * 4;   // physical slot of logical chunk tig

    const half* p0 = xs + rA * XS_STRIDE;
    const half* p8 = p0 + 8 * XS_STRIDE;

    float c[4][4];
#pragma unroll
    for (int j = 0; j < 4; j++)
#pragma unroll
        for (int q = 0; q < 4; q++) c[j][q] = 0.f;

#pragma unroll
    for (int ks = 0; ks < 8; ks++) {
        int o = ks * 16 + soff;
        uint2 A0 = *(const uint2*)(p0 + o);   // .x=(rA, k 2t:2t+1) .y=(rA, k 2t+8:+9)
        uint2 A1 = *(const uint2*)(p8 + o);
#pragma unroll
        for (int j = 0; j < 4; j++) {
            int n = n0 + j * 8 + grp;
            uint2 b = g_Whp[n * 32 + ks * 4 + tig];
            asm("mma.sync.aligned.m16n8k16.row.col.f32.f16.f16.f32 "
                "{%0,%1,%2,%3}, {%4,%5,%6,%7}, {%8,%9}, {%0,%1,%2,%3};"
                : "+f"(c[j][0]), "+f"(c[j][1]), "+f"(c[j][2]), "+f"(c[j][3])
                : "r"(A0.x), "r"(A1.x), "r"(A0.y), "r"(A1.y), "r"(b.x), "r"(b.y));
        }
    }

    // epilogue: 2 rows per thread-quad: rA, rA+8
#pragma unroll
    for (int rt = 0; rt < 2; rt++) {
        int row = blk0 + rA + rt * 8;
        float2 v[4];
#pragma unroll
        for (int j = 0; j < 4; j++)
            v[j] = (rt == 0) ? make_float2(c[j][0], c[j][1]) : make_float2(c[j][2], c[j][3]);
        float ps = 0.f, pd = 0.f;
#pragma unroll
        for (int j = 0; j < 4; j++) {
            int col = j * 8 + tig * 2;
            ps += v[j].x * att_src[n0 + col] + v[j].y * att_src[n0 + col + 1];
            pd += v[j].x * att_dst[n0 + col] + v[j].y * att_dst[n0 + col + 1];
        }
#pragma unroll
        for (int o = 1; o < 4; o <<= 1) {
            ps += __shfl_xor_sync(0xFFFFFFFFu, ps, o);
            pd += __shfl_xor_sync(0xFFFFFFFFu, pd, o);
        }
        if (row < NN) {
            if (tig == 0) { g_asrc[row * 4 + head] = ps; g_adst[row * 4 + head] = pd; }
#pragma unroll
            for (int j = 0; j < 4; j++) {
                half2 hp = __floats2half2_rn(v[j].x, v[j].y);
                g_hh[(size_t)row * 64 + (n0 + j * 8 + tig * 2) / 2] = *(unsigned int*)&hp;
            }
        }
    }
}

// ---------------- kernel 2: gemm part A || degree count ----------------------
__global__ __launch_bounds__(256) void gemm_count_kernel(
    const float* __restrict__ x,
    const float* __restrict__ att_src, const float* __restrict__ att_dst,
    const void* __restrict__ eiv) {
    __shared__ __align__(16) half xs[BM * XS_STRIDE];
    if (blockIdx.x < NG1) { gemm_tile(blockIdx.x * BM, threadIdx.x, xs, x, att_src, att_dst); return; }
    int t = (blockIdx.x - NG1) * 256 + threadIdx.x;
    if (t < EE) {
        int dst;
        if (g_is64) dst = (int)((const long long*)eiv)[EE + t];
        else        dst = ((const int*)eiv)[EE + t];
        atomicAdd(&g_deg[dst], 1);
    }
}

// ---------------- kernel 3: single-kernel scan (decoupled lookback) ----------
__global__ __launch_bounds__(1024) void scan_fused_kernel() {
    __shared__ int sm[1024];
    __shared__ int s_off;
    const int bid = blockIdx.x, tid = threadIdx.x;
    const int i = bid * 1024 + tid;
    int v = 0;
    if (i < NN) { v = g_deg[i] + 1; g_deg[i] = 0; }  // +1 self loop; reset for replay
    sm[tid] = v;
    __syncthreads();
    for (int o = 1; o < 1024; o <<= 1) {
        int t = (tid >= (unsigned)o) ? sm[tid - o] : 0;
        __syncthreads();
        sm[tid] += t;
        __syncthreads();
    }
    int incl = sm[tid];

    if (tid == 1023)
        atomicExch(&g_lb[bid], (1ULL << 32) | (unsigned long long)(unsigned)incl);

    if (tid < 32) {
        int sum = 0;
        for (int j = tid; j < bid; j += 32) {
            unsigned long long p;
            do { p = *((volatile unsigned long long*)&g_lb[j]); } while (!(p >> 32));
            sum += (int)(unsigned)p;
        }
#pragma unroll
        for (int o = 16; o > 0; o >>= 1) sum += __shfl_xor_sync(0xFFFFFFFFu, sum, o);
        if (tid == 0) s_off = sum;
    }
    __syncthreads();

    if (i < NN) {
        int rs = s_off + incl - v;
        g_rowstart[i] = rs;
        g_cursor[i]   = rs;
    }
    if (bid == NB_SCAN - 1 && tid == 1023) g_rowstart[NN] = EE + NN;
}

// ---------------- kernel 4: gemm part B || CSR scatter ------------------------
__global__ __launch_bounds__(256) void gemm_scatter_kernel(
    const float* __restrict__ x,
    const float* __restrict__ att_src, const float* __restrict__ att_dst,
    const void* __restrict__ eiv) {
    __shared__ __align__(16) half xs[BM * XS_STRIDE];
    if (blockIdx.x < NG2) { gemm_tile((NG1 + blockIdx.x) * BM, threadIdx.x, xs, x, att_src, att_dst); return; }
    int t = (blockIdx.x - NG2) * 256 + threadIdx.x;
    if (t >= EE + NN) return;
    int s, d;
    if (t < EE) {
        if (g_is64) {
            s = (int)((const long long*)eiv)[t];
            d = (int)((const long long*)eiv)[EE + t];
        } else {
            s = ((const int*)eiv)[t];
            d = ((const int*)eiv)[EE + t];
        }
    } else {
        s = d = t - EE;  // self loop
    }
    int p = atomicAdd(&g_cursor[d], 1);
    g_srcs[p] = s;
}

// ---------------- kernel 5: softmax + aggregation, 2 nodes per warp ----------
__global__ __launch_bounds__(256) void aggregate_kernel(
    const float* __restrict__ bias, float* __restrict__ out) {
    const int grp = threadIdx.x >> 4;
    const int l   = threadIdx.x & 15;
    const int i = blockIdx.x * 16 + grp;
    if (i >= NN) return;

    const int head = l >> 2;
    const float adst = g_adst[i * 4 + head];
    const int start = g_rowstart[i];
    const int end   = g_rowstart[i + 1];

    float acc[8];
#pragma unroll
    for (int q = 0; q < 8; q++) acc[q] = 0.f;
    float ssum = 0.f;

    int src_next = g_srcs[start];
    for (int j = start; j < end; j++) {
        int src = src_next;
        if (j + 1 < end) src_next = g_srcs[j + 1];
        float e = g_asrc[src * 4 + head] + adst;
        e = (e > 0.f) ? e : 0.2f * e;
        float w = __expf(e);
        uint4 hp = *(const uint4*)(g_hh + (size_t)src * 64 + l * 4);  // 8 halves
        float2 f0 = __half22float2(*(const half2*)&hp.x);
        float2 f1 = __half22float2(*(const half2*)&hp.y);
        float2 f2 = __half22float2(*(const half2*)&hp.z);
        float2 f3 = __half22float2(*(const half2*)&hp.w);
        ssum += w;
        acc[0] += w * f0.x; acc[1] += w * f0.y;
        acc[2] += w * f1.x; acc[3] += w * f1.y;
        acc[4] += w * f2.x; acc[5] += w * f2.y;
        acc[6] += w * f3.x; acc[7] += w * f3.y;
    }

    float inv = 1.f / ssum;
    float4 b0 = *(const float4*)(bias + l * 8);
    float4 b1 = *(const float4*)(bias + l * 8 + 4);
    float4 o0, o1;
    o0.x = acc[0] * inv + b0.x; o0.y = acc[1] * inv + b0.y;
    o0.z = acc[2] * inv + b0.z; o0.w = acc[3] * inv + b0.w;
    o1.x = acc[4] * inv + b1.x; o1.y = acc[5] * inv + b1.y;
    o1.z = acc[6] * inv + b1.z; o1.w = acc[7] * inv + b1.w;
    *(float4*)(out + (size_t)i * HF + l * 8)     = o0;
    *(float4*)(out + (size_t)i * HF + l * 8 + 4) = o1;
}

// ---------------- launch ----------------
extern "C" void kernel_launch(void* const* d_in, const int* in_sizes, int n_in,
                              void* d_out, int out_size) {
    const float* x    = (const float*)d_in[0];
    const void*  ei   = d_in[1];
    const float* W    = (const float*)d_in[2];
    const float* asv  = (const float*)d_in[3];
    const float* adv  = (const float*)d_in[4];
    const float* bias = (const float*)d_in[5];
    float* out = (float*)d_out;

    pack_kernel<<<17, 256>>>((const int*)ei, W);
    gemm_count_kernel<<<NG1 + NCOUNT, 256>>>(x, asv, adv, ei);
    scan_fused_kernel<<<NB_SCAN, 1024>>>();
    gemm_scatter_kernel<<<NG2 + NSCAT, 256>>>(x, asv, adv, ei);
    aggregate_kernel<<<(NN + 15) / 16, 256>>>(bias, out);
}

// round 16
// speedup vs baseline: 1.0327x; 1.0327x over previous
#include <cuda_runtime.h>
#include <cuda_fp16.h>
#include <cstdint>

#define NN 100000
#define EE 1600000
#define HF 128           // HEADS * OUT_F
#define NB_SCAN 98       // ceil(NN/1024)
#define BM 64            // rows per gemm block
#define NGEMM 1563       // ceil(NN/64) total gemm blocks
#define NG1 600          // gemm blocks in launch A
#define NG2 (NGEMM - NG1) // 963 gemm blocks in launch B
#define NCOUNT 6250      // ceil(EE/256)
#define NSCAT 6641       // ceil((EE+NN)/256)
#define K1 12            // interleave period launch A: 1 gemm : 11 count
#define K2 8             // interleave period launch B: 1 gemm : 7 scatter
#define XS_STRIDE 144    // halves per row (128 + 16 pad)

// ---------------- scratch (statics zero-initialized at load) -----------------
__device__ unsigned int g_hh[NN * 64]; // 25.6 MB : h in half2 (64 x uint per row)
__device__ float  g_asrc[NN * 4];
__device__ float  g_adst[NN * 4];
__device__ int    g_deg[NN];           // scan re-zeroes after use (replay-safe)
__device__ int    g_cursor[NN];
__device__ int    g_rowstart[NN + 1];
__device__ int    g_srcs[EE + NN];
__device__ unsigned long long g_lb[NB_SCAN];  // lookback: (flag<<32)|blocksum
__device__ uint2  g_Whp[128 * 8 * 4];  // W in fp16 B-fragment order (32 KB)
__device__ int    g_is64;

// ---------------- kernel 1: detect + lb clear + W fp16 fragment pack ---------
__global__ __launch_bounds__(256) void pack_kernel(
    const int* ei32, const float* __restrict__ W) {
    const int bid = blockIdx.x, tid = threadIdx.x;
    if (bid == 0) {
        __shared__ int nz;
        if (tid == 0) nz = 0;
        __syncthreads();
        if (ei32[tid * 2 + 1] != 0) atomicAdd(&nz, 1);  // odd words zero => int64
        __syncthreads();
        if (tid == 0) g_is64 = (nz == 0) ? 1 : 0;
        if (tid < NB_SCAN) g_lb[tid] = 0ULL;
        return;
    }
    int e = (bid - 1) * 256 + tid;       // < 4096 : (n, ks, tig)
    int n = e >> 5, r = e & 31, ks = r >> 2, tg = r & 3;
    int k0 = ks * 16 + tg * 2;
    half2 lo = __floats2half2_rn(W[k0 * HF + n],       W[(k0 + 1) * HF + n]);
    half2 hi = __floats2half2_rn(W[(k0 + 8) * HF + n], W[(k0 + 9) * HF + n]);
    g_Whp[e] = make_uint2(*(unsigned int*)&lo, *(unsigned int*)&hi);
}

// ---------------- GEMM tile body: fp16 mma m16n8k16, 256 thr, 8 warps --------
// warp tile 32x32: wm = warp>>2 (m half), head = warp&3 (32 cols)
// smem: per row 128 halves permuted so LDS.64 yields fragment pairs;
// 4-slot XOR swizzle (slot ^= row&3) -> 2-way-floor bank access
__device__ __forceinline__ void gemm_tile(
    int blk0, int tid, half* xs, const float* __restrict__ x,
    const float* __restrict__ att_src, const float* __restrict__ att_dst) {
#pragma unroll
    for (int it = 0; it < 8; it++) {
        int fidx = it * 256 + tid;            // float4 index, 2048 total
        int row = fidx >> 5, c4 = (fidx & 31) * 4;
        float4 v = make_float4(0.f, 0.f, 0.f, 0.f);
        if (blk0 + row < NN) v = *(const float4*)(x + (size_t)(blk0 + row) * HF + c4);
        int base = c4 & ~15;
        int q  = (c4 >> 1) & 3;               // logical slot of (k, k+1)
        int h2 = (c4 >> 3) & 1;               // within-slot offset (k vs k+8 group)
        int sw = row & 3;
        half* rp = xs + row * XS_STRIDE + base;
        *(half2*)(rp + (q ^ sw) * 4 + h2 * 2)       = __floats2half2_rn(v.x, v.y);
        *(half2*)(rp + ((q + 1) ^ sw) * 4 + h2 * 2) = __floats2half2_rn(v.z, v.w);
    }
    __syncthreads();

    const int warp = tid >> 5, lane = tid & 31;
    const int grp = lane >> 2, tig = lane & 3;
    const int wm = warp >> 2, head = warp & 3;
    const int n0 = head * 32;
    const int rA = wm * 32 + grp;
    const int soff = (tig ^ (grp & 3)) * 4;   // physical slot of logical chunk tig

    const half* p0  = xs + rA * XS_STRIDE;
    const half* p8  = p0 + 8 * XS_STRIDE;
    const half* p16 = p0 + 16 * XS_STRIDE;
    const half* p24 = p0 + 24 * XS_STRIDE;

    float c0[4][4], c1[4][4];
#pragma unroll
    for (int j = 0; j < 4; j++)
#pragma unroll
        for (int q = 0; q < 4; q++) { c0[j][q] = 0.f; c1[j][q] = 0.f; }

#pragma unroll
    for (int ks = 0; ks < 8; ks++) {
        int o = ks * 16 + soff;
        uint2 A0 = *(const uint2*)(p0 + o);
        uint2 A1 = *(const uint2*)(p8 + o);
        uint2 A2 = *(const uint2*)(p16 + o);
        uint2 A3 = *(const uint2*)(p24 + o);
#pragma unroll
        for (int j = 0; j < 4; j++) {
            int n = n0 + j * 8 + grp;
            uint2 b = g_Whp[n * 32 + ks * 4 + tig];
            asm("mma.sync.aligned.m16n8k16.row.col.f32.f16.f16.f32 "
                "{%0,%1,%2,%3}, {%4,%5,%6,%7}, {%8,%9}, {%0,%1,%2,%3};"
                : "+f"(c0[j][0]), "+f"(c0[j][1]), "+f"(c0[j][2]), "+f"(c0[j][3])
                : "r"(A0.x), "r"(A1.x), "r"(A0.y), "r"(A1.y), "r"(b.x), "r"(b.y));
            asm("mma.sync.aligned.m16n8k16.row.col.f32.f16.f16.f32 "
                "{%0,%1,%2,%3}, {%4,%5,%6,%7}, {%8,%9}, {%0,%1,%2,%3};"
                : "+f"(c1[j][0]), "+f"(c1[j][1]), "+f"(c1[j][2]), "+f"(c1[j][3])
                : "r"(A2.x), "r"(A3.x), "r"(A2.y), "r"(A3.y), "r"(b.x), "r"(b.y));
        }
    }

    // epilogue: 4 rows per thread-quad: rA, rA+8, rA+16, rA+24
#pragma unroll
    for (int rt = 0; rt < 4; rt++) {
        int row = blk0 + rA + rt * 8;
        float2 v[4];
#pragma unroll
        for (int j = 0; j < 4; j++) {
            float lo = (rt == 0) ? c0[j][0] : (rt == 1) ? c0[j][2] : (rt == 2) ? c1[j][0] : c1[j][2];
            float hi = (rt == 0) ? c0[j][1] : (rt == 1) ? c0[j][3] : (rt == 2) ? c1[j][1] : c1[j][3];
            v[j] = make_float2(lo, hi);
        }
        float ps = 0.f, pd = 0.f;
#pragma unroll
        for (int j = 0; j < 4; j++) {
            int col = j * 8 + tig * 2;
            ps += v[j].x * att_src[n0 + col] + v[j].y * att_src[n0 + col + 1];
            pd += v[j].x * att_dst[n0 + col] + v[j].y * att_dst[n0 + col + 1];
        }
#pragma unroll
        for (int o = 1; o < 4; o <<= 1) {
            ps += __shfl_xor_sync(0xFFFFFFFFu, ps, o);
            pd += __shfl_xor_sync(0xFFFFFFFFu, pd, o);
        }
        if (row < NN) {
            if (tig == 0) { g_asrc[row * 4 + head] = ps; g_adst[row * 4 + head] = pd; }
#pragma unroll
            for (int j = 0; j < 4; j++) {
                half2 hp = __floats2half2_rn(v[j].x, v[j].y);
                g_hh[(size_t)row * 64 + (n0 + j * 8 + tig * 2) / 2] = *(unsigned int*)&hp;
            }
        }
    }
}

// ---------------- kernel 2: gemm part A ||| degree count (interleaved) -------
// bid % K1 == 0 -> gemm tile; else count chunk. Every wave carries both roles.
__global__ __launch_bounds__(256) void gemm_count_kernel(
    const float* __restrict__ x,
    const float* __restrict__ att_src, const float* __restrict__ att_dst,
    const void* __restrict__ eiv) {
    __shared__ __align__(16) half xs[BM * XS_STRIDE];
    const int g = blockIdx.x / K1, r = blockIdx.x % K1;
    if (r == 0) { gemm_tile(g * BM, threadIdx.x, xs, x, att_src, att_dst); return; }
    int cidx = g * (K1 - 1) + (r - 1);
    int t = cidx * 256 + threadIdx.x;
    if (cidx < NCOUNT && t < EE) {
        int dst;
        if (g_is64) dst = (int)((const long long*)eiv)[EE + t];
        else        dst = ((const int*)eiv)[EE + t];
        atomicAdd(&g_deg[dst], 1);
    }
}

// ---------------- kernel 3: single-kernel scan (decoupled lookback) ----------
__global__ __launch_bounds__(1024) void scan_fused_kernel() {
    __shared__ int sm[1024];
    __shared__ int s_off;
    const int bid = blockIdx.x, tid = threadIdx.x;
    const int i = bid * 1024 + tid;
    int v = 0;
    if (i < NN) { v = g_deg[i] + 1; g_deg[i] = 0; }  // +1 self loop; reset for replay
    sm[tid] = v;
    __syncthreads();
    for (int o = 1; o < 1024; o <<= 1) {
        int t = (tid >= (unsigned)o) ? sm[tid - o] : 0;
        __syncthreads();
        sm[tid] += t;
        __syncthreads();
    }
    int incl = sm[tid];

    if (tid == 1023)
        atomicExch(&g_lb[bid], (1ULL << 32) | (unsigned long long)(unsigned)incl);

    if (tid < 32) {
        int sum = 0;
        for (int j = tid; j < bid; j += 32) {
            unsigned long long p;
            do { p = *((volatile unsigned long long*)&g_lb[j]); } while (!(p >> 32));
            sum += (int)(unsigned)p;
        }
#pragma unroll
        for (int o = 16; o > 0; o >>= 1) sum += __shfl_xor_sync(0xFFFFFFFFu, sum, o);
        if (tid == 0) s_off = sum;
    }
    __syncthreads();

    if (i < NN) {
        int rs = s_off + incl - v;
        g_rowstart[i] = rs;
        g_cursor[i]   = rs;
    }
    if (bid == NB_SCAN - 1 && tid == 1023) g_rowstart[NN] = EE + NN;
}

// ---------------- kernel 4: gemm part B ||| CSR scatter (interleaved) --------
__global__ __launch_bounds__(256) void gemm_scatter_kernel(
    const float* __restrict__ x,
    const float* __restrict__ att_src, const float* __restrict__ att_dst,
    const void* __restrict__ eiv) {
    __shared__ __align__(16) half xs[BM * XS_STRIDE];
    const int g = blockIdx.x / K2, r = blockIdx.x % K2;
    if (r == 0) { gemm_tile((NG1 + g) * BM, threadIdx.x, xs, x, att_src, att_dst); return; }
    int sidx = g * (K2 - 1) + (r - 1);
    int t = sidx * 256 + threadIdx.x;
    if (sidx >= NSCAT || t >= EE + NN) return;
    int s, d;
    if (t < EE) {
        if (g_is64) {
            s = (int)((const long long*)eiv)[t];
            d = (int)((const long long*)eiv)[EE + t];
        } else {
            s = ((const int*)eiv)[t];
            d = ((const int*)eiv)[EE + t];
        }
    } else {
        s = d = t - EE;  // self loop
    }
    int p = atomicAdd(&g_cursor[d], 1);
    g_srcs[p] = s;
}

// ---------------- kernel 5: softmax + aggregation, 2 nodes per warp ----------
__global__ __launch_bounds__(256) void aggregate_kernel(
    const float* __restrict__ bias, float* __restrict__ out) {
    const int grp = threadIdx.x >> 4;
    const int l   = threadIdx.x & 15;
    const int i = blockIdx.x * 16 + grp;
    if (i >= NN) return;

    const int head = l >> 2;
    const float adst = g_adst[i * 4 + head];
    const int start = g_rowstart[i];
    const int end   = g_rowstart[i + 1];

    float acc[8];
#pragma unroll
    for (int q = 0; q < 8; q++) acc[q] = 0.f;
    float ssum = 0.f;

    int src_next = g_srcs[start];
    for (int j = start; j < end; j++) {
        int src = src_next;
        if (j + 1 < end) src_next = g_srcs[j + 1];
        float e = g_asrc[src * 4 + head] + adst;
        e = (e > 0.f) ? e : 0.2f * e;
        float w = __expf(e);
        uint4 hp = *(const uint4*)(g_hh + (size_t)src * 64 + l * 4);  // 8 halves
        float2 f0 = __half22float2(*(const half2*)&hp.x);
        float2 f1 = __half22float2(*(const half2*)&hp.y);
        float2 f2 = __half22float2(*(const half2*)&hp.z);
        float2 f3 = __half22float2(*(const half2*)&hp.w);
        ssum += w;
        acc[0] += w * f0.x; acc[1] += w * f0.y;
        acc[2] += w * f1.x; acc[3] += w * f1.y;
        acc[4] += w * f2.x; acc[5] += w * f2.y;
        acc[6] += w * f3.x; acc[7] += w * f3.y;
    }

    float inv = 1.f / ssum;
    float4 b0 = *(const float4*)(bias + l * 8);
    float4 b1 = *(const float4*)(bias + l * 8 + 4);
    float4 o0, o1;
    o0.x = acc[0] * inv + b0.x; o0.y = acc[1] * inv + b0.y;
    o0.z = acc[2] * inv + b0.z; o0.w = acc[3] * inv + b0.w;
    o1.x = acc[4] * inv + b1.x; o1.y = acc[5] * inv + b1.y;
    o1.z = acc[6] * inv + b1.z; o1.w = acc[7] * inv + b1.w;
    *(float4*)(out + (size_t)i * HF + l * 8)     = o0;
    *(float4*)(out + (size_t)i * HF + l * 8 + 4) = o1;
}

// ---------------- launch ----------------
extern "C" void kernel_launch(void* const* d_in, const int* in_sizes, int n_in,
                              void* d_out, int out_size) {
    const float* x    = (const float*)d_in[0];
    const void*  ei   = d_in[1];
    const float* W    = (const float*)d_in[2];
    const float* asv  = (const float*)d_in[3];
    const float* adv  = (const float*)d_in[4];
    const float* bias = (const float*)d_in[5];
    float* out = (float*)d_out;

    pack_kernel<<<17, 256>>>((const int*)ei, W);
    gemm_count_kernel<<<NG1 * K1, 256>>>(x, asv, adv, ei);        // 7200 blocks
    scan_fused_kernel<<<NB_SCAN, 1024>>>();
    gemm_scatter_kernel<<<NG2 * K2, 256>>>(x, asv, adv, ei);      // 7704 blocks
    aggregate_kernel<<<(NN + 15) / 16, 256>>>(bias, out);
}